// round 13
// baseline (speedup 1.0000x reference)
#include <cuda_runtime.h>
#include <cuda_fp16.h>
#include <cstdint>

#define E_       8
#define TOPK_    2
#define HID_     1024
#define FFN_     2048
#define M_TOK    2048
#define NSLOT    (M_TOK * TOPK_)      // 4096
#define OUT_MAIN (M_TOK * HID_)       // 2097152

#define BK    32
#define LDSW  40                      // smem row stride in halves (80B)
#define ROWB  80
#define ABUF  (128 * ROWB)            // 10240 B per operand tile
#define STAGE (2 * ABUF)              // 20480 B per stage (A + B)
#define NSTG  4

// ---------------- device scratch ----------------
__device__ int    g_cnt[E_];
__device__ int    g_off[E_ + 1];
__device__ int    g_cur[E_];
__device__ int    g_slot_e[NSLOT];
__device__ float  g_slot_w[NSLOT];
__device__ int    g_tok[NSLOT];
__device__ float  g_w[NSLOT];
__device__ __half g_hh[(size_t)NSLOT * FFN_];
__device__ __half g_xh[(size_t)M_TOK * HID_];
__device__ __half g_w1h[(size_t)E_ * 2 * FFN_ * HID_];
__device__ __half g_w2h[(size_t)E_ * HID_ * FFN_];

// ---------------- helpers ----------------
__device__ __forceinline__ void mma_f16(float* d, const uint32_t* a,
                                        const uint32_t* b, const float* c) {
    asm("mma.sync.aligned.m16n8k16.row.col.f32.f16.f16.f32 "
        "{%0,%1,%2,%3}, {%4,%5,%6,%7}, {%8,%9}, {%10,%11,%12,%13};\n"
        : "=f"(d[0]), "=f"(d[1]), "=f"(d[2]), "=f"(d[3])
        : "r"(a[0]), "r"(a[1]), "r"(a[2]), "r"(a[3]),
          "r"(b[0]), "r"(b[1]),
          "f"(c[0]), "f"(c[1]), "f"(c[2]), "f"(c[3]));
}
__device__ __forceinline__ void ldsm_x4(uint32_t& r0, uint32_t& r1,
                                        uint32_t& r2, uint32_t& r3, uint32_t addr) {
    asm volatile("ldmatrix.sync.aligned.m8n8.x4.shared.b16 {%0,%1,%2,%3}, [%4];"
                 : "=r"(r0), "=r"(r1), "=r"(r2), "=r"(r3) : "r"(addr));
}
__device__ __forceinline__ void cpa16(uint32_t saddr, const void* g) {
    asm volatile("cp.async.cg.shared.global [%0], [%1], 16;\n" :: "r"(saddr), "l"(g));
}
__device__ __forceinline__ void cpa_commit() { asm volatile("cp.async.commit_group;\n"); }
__device__ __forceinline__ void cpa_wait3()  { asm volatile("cp.async.wait_group 3;\n"); }
__device__ __forceinline__ void cpa_wait2()  { asm volatile("cp.async.wait_group 2;\n"); }
__device__ __forceinline__ void cpa_wait1()  { asm volatile("cp.async.wait_group 1;\n"); }
__device__ __forceinline__ void cpa_wait0()  { asm volatile("cp.async.wait_group 0;\n"); }
__device__ __forceinline__ uint32_t smem_u32(const void* p) {
    return (uint32_t)__cvta_generic_to_shared(p);
}

// ---------------- router (float4 loads) + fused x->fp16 ----------------
__global__ void k_router(const float* __restrict__ x,
                         const float* __restrict__ rw,
                         const float* __restrict__ rb,
                         float* __restrict__ out) {
    int warp = (blockIdx.x * blockDim.x + threadIdx.x) >> 5;
    int lane = threadIdx.x & 31;
    if (warp >= M_TOK) return;

    const float4* xr4 = (const float4*)(x + (size_t)warp * HID_);
    float4 xv[8];
#pragma unroll
    for (int j = 0; j < 8; j++) xv[j] = xr4[lane + 32 * j];

    // fused fp16 copy of x
    uint2* xh2 = (uint2*)(g_xh + (size_t)warp * HID_);
#pragma unroll
    for (int j = 0; j < 8; j++) {
        __half2 lo = __floats2half2_rn(xv[j].x, xv[j].y);
        __half2 hi = __floats2half2_rn(xv[j].z, xv[j].w);
        uint2 o; o.x = *(uint32_t*)&lo; o.y = *(uint32_t*)&hi;
        xh2[lane + 32 * j] = o;
    }

    float logits[E_];
#pragma unroll
    for (int e = 0; e < E_; e++) {
        const float4* w4 = (const float4*)(rw + (size_t)e * HID_);
        float acc = 0.0f;
#pragma unroll
        for (int j = 0; j < 8; j++) {
            float4 w = w4[lane + 32 * j];
            acc += xv[j].x * w.x + xv[j].y * w.y + xv[j].z * w.z + xv[j].w * w.w;
        }
#pragma unroll
        for (int o = 16; o > 0; o >>= 1) acc += __shfl_xor_sync(0xffffffffu, acc, o);
        logits[e] = acc + rb[e];
    }

    if (lane == 0) {
        float mx = logits[0];
#pragma unroll
        for (int e = 1; e < E_; e++) mx = fmaxf(mx, logits[e]);
        float p[E_], s = 0.0f;
#pragma unroll
        for (int e = 0; e < E_; e++) { p[e] = expf(logits[e] - mx); s += p[e]; }
        float inv = 1.0f / s;
#pragma unroll
        for (int e = 0; e < E_; e++) p[e] *= inv;

        int i0 = 0;
#pragma unroll
        for (int e = 1; e < E_; e++) if (p[e] > p[i0]) i0 = e;
        int i1 = -1;
#pragma unroll
        for (int e = 0; e < E_; e++) {
            if (e == i0) continue;
            if (i1 < 0 || p[e] > p[i1]) i1 = e;
        }

        out[OUT_MAIN + warp * 2 + 0] = p[i0];
        out[OUT_MAIN + warp * 2 + 1] = p[i1];
        g_slot_e[warp * 2 + 0] = i0;  g_slot_w[warp * 2 + 0] = p[i0];
        g_slot_e[warp * 2 + 1] = i1;  g_slot_w[warp * 2 + 1] = p[i1];
        atomicAdd(&g_cnt[i0], 1);
        atomicAdd(&g_cnt[i1], 1);
    }
}

// scan: compute offsets, reset counters for next replay
__global__ void k_scan() {
    if (threadIdx.x == 0) {
        int s = 0;
        for (int e = 0; e < E_; e++) { g_off[e] = s; g_cur[e] = s; s += g_cnt[e]; g_cnt[e] = 0; }
        g_off[E_] = s;
    }
}

__global__ void k_place() {
    int s = blockIdx.x * blockDim.x + threadIdx.x;
    if (s >= NSLOT) return;
    int e = g_slot_e[s];
    int p = atomicAdd(&g_cur[e], 1);
    g_tok[p] = s >> 1;
    g_w[p]   = g_slot_w[s];
}

// fp32 -> fp16 streaming convert (RN)
__global__ void k_cvt_h(const float4* __restrict__ src, uint2* __restrict__ dst, int n4) {
    int i = blockIdx.x * blockDim.x + threadIdx.x;
    int stride = gridDim.x * blockDim.x;
    for (; i < n4; i += stride) {
        float4 v = src[i];
        __half2 lo = __floats2half2_rn(v.x, v.y);
        __half2 hi = __floats2half2_rn(v.z, v.w);
        uint2 o;
        o.x = *(uint32_t*)&lo;
        o.y = *(uint32_t*)&hi;
        dst[i] = o;
    }
}

// zero out region (runs on s2)
__global__ void k_zout(float* __restrict__ out) {
    int i = blockIdx.x * blockDim.x + threadIdx.x;
    for (int j = i; j < OUT_MAIN; j += gridDim.x * blockDim.x) out[j] = 0.0f;
}

// ============================================================================
// GEMM1 (fp16 HMMA + ldmatrix): h = silu(x@Wg^T + bg) * (x@Wu^T + bu)
// ebase selects the expert group (launched in two halves).
// ============================================================================
__global__ void __launch_bounds__(256, 2)
k_gemm1(const float* __restrict__ w1b, int ebase) {
    int e = ebase + blockIdx.z;
    int rowEnd = g_off[e + 1];
    int row0 = g_off[e] + blockIdx.y * 128;
    if (row0 >= rowEnd) return;
    int nb = blockIdx.x * 64;

    extern __shared__ __half dsm[];
    __shared__ const __half* s_aptr[128];

    int tid  = threadIdx.x;
    int lane = tid & 31;
    int wid  = tid >> 5;
    int wm   = wid >> 2;
    int wn   = wid & 3;
    uint32_t sbase = smem_u32(dsm);

    for (int r = tid; r < 128; r += 256) {
        int gr = row0 + r;
        if (gr >= rowEnd) gr = rowEnd - 1;
        s_aptr[r] = g_xh + (size_t)g_tok[gr] * HID_;
    }
    __syncthreads();

    int rI[2], cI[2];
    const __half* bp[2];
#pragma unroll
    for (int i = 0; i < 2; i++) {
        int idx = tid + 256 * i;
        rI[i] = idx >> 2;
        cI[i] = (idx & 3) * 8;
        int r = rI[i];
        size_t wrow = (size_t)e * 2 * FFN_ + ((r & 1) ? (FFN_ + nb + (r >> 1)) : (nb + (r >> 1)));
        bp[i] = g_w1h + wrow * HID_;
    }

    auto load_tile = [&](int s, int k0) {
        uint32_t st = sbase + s * STAGE;
#pragma unroll
        for (int i = 0; i < 2; i++) {
            uint32_t off = (uint32_t)(rI[i] * LDSW + cI[i]) * 2;
            cpa16(st + off,        s_aptr[rI[i]] + k0 + cI[i]);
            cpa16(st + ABUF + off, bp[i] + k0 + cI[i]);
        }
        cpa_commit();
    };

    float acc[4][4][4];
#pragma unroll
    for (int mi = 0; mi < 4; mi++)
#pragma unroll
        for (int ni = 0; ni < 4; ni++)
#pragma unroll
            for (int q = 0; q < 4; q++) acc[mi][ni][q] = 0.0f;

    const int NT = HID_ / BK;   // 32
    load_tile(0, 0);
    load_tile(1, BK);
    load_tile(2, 2 * BK);

    int lr = lane >> 2;
    int lc = lane & 3;

    uint32_t a_loff = (uint32_t)((lane & 15) * ROWB + ((lane >> 4) & 1) * 16)
                    + (uint32_t)(wm * 64 * ROWB);
    uint32_t b_loff = (uint32_t)((((lane >> 4) & 1) * 8 + (lane & 7)) * ROWB
                    + ((lane >> 3) & 1) * 16)
                    + (uint32_t)(wn * 32 * ROWB);

    for (int kt = 0; kt < NT; kt++) {
        int buf = kt & (NSTG - 1);
        if (kt + 3 < NT)      { load_tile((kt + 3) & (NSTG - 1), (kt + 3) * BK); cpa_wait3(); }
        else if (kt + 2 < NT) { cpa_wait2(); }
        else if (kt + 1 < NT) { cpa_wait1(); }
        else                  { cpa_wait0(); }
        __syncthreads();

        uint32_t At = sbase + buf * STAGE;
        uint32_t Bt = At + ABUF;
#pragma unroll
        for (int s = 0; s < 2; s++) {
            uint32_t ks = s * 32;
            uint32_t a[4][4], b[4][2];
#pragma unroll
            for (int mi = 0; mi < 4; mi++)
                ldsm_x4(a[mi][0], a[mi][1], a[mi][2], a[mi][3],
                        At + (uint32_t)(mi * 16 * ROWB) + ks + a_loff);
#pragma unroll
            for (int nj = 0; nj < 2; nj++)
                ldsm_x4(b[2 * nj][0], b[2 * nj][1], b[2 * nj + 1][0], b[2 * nj + 1][1],
                        Bt + (uint32_t)(nj * 16 * ROWB) + ks + b_loff);
#pragma unroll
            for (int mi = 0; mi < 4; mi++)
#pragma unroll
                for (int ni = 0; ni < 4; ni++)
                    mma_f16(acc[mi][ni], a[mi], b[ni], acc[mi][ni]);
        }
        __syncthreads();
    }

    const float* bg_base = w1b + (size_t)e * 2 * FFN_;
    const float* bu_base = bg_base + FFN_;
#pragma unroll
    for (int mi = 0; mi < 4; mi++) {
        int r = row0 + wm * 64 + mi * 16 + lr;
#pragma unroll
        for (int ni = 0; ni < 4; ni++) {
            int gj = nb + wn * 16 + ni * 4 + lc;
            float bg = bg_base[gj];
            float bu = bu_base[gj];
            if (r < rowEnd) {
                float g = acc[mi][ni][0] + bg;
                float u = acc[mi][ni][1] + bu;
                g_hh[(size_t)r * FFN_ + gj] = __float2half_rn((g / (1.0f + expf(-g))) * u);
            }
            if (r + 8 < rowEnd) {
                float g = acc[mi][ni][2] + bg;
                float u = acc[mi][ni][3] + bu;
                g_hh[(size_t)(r + 8) * FFN_ + gj] = __float2half_rn((g / (1.0f + expf(-g))) * u);
            }
        }
    }
}

// ============================================================================
// GEMM2 (fp16 HMMA + ldmatrix): out[tok] += w * (h@W2^T + b2)
// ============================================================================
__global__ void __launch_bounds__(256, 2)
k_gemm2(const float* __restrict__ w2b, float* __restrict__ out) {
    int e = blockIdx.z;
    int rowEnd = g_off[e + 1];
    int row0 = g_off[e] + blockIdx.y * 128;
    if (row0 >= rowEnd) return;
    int nb = blockIdx.x * 128;

    extern __shared__ __half dsm[];

    int tid  = threadIdx.x;
    int lane = tid & 31;
    int wid  = tid >> 5;
    int wm   = wid >> 2;
    int wn   = wid & 3;
    uint32_t sbase = smem_u32(dsm);

    int rI[2], cI[2];
    const __half* ap[2];
    const __half* bp[2];
#pragma unroll
    for (int i = 0; i < 2; i++) {
        int idx = tid + 256 * i;
        rI[i] = idx >> 2;
        cI[i] = (idx & 3) * 8;
        int gr = row0 + rI[i];
        if (gr >= rowEnd) gr = rowEnd - 1;
        ap[i] = g_hh + (size_t)gr * FFN_;
        bp[i] = g_w2h + ((size_t)e * HID_ + (nb + rI[i])) * FFN_;
    }

    auto load_tile = [&](int s, int k0) {
        uint32_t st = sbase + s * STAGE;
#pragma unroll
        for (int i = 0; i < 2; i++) {
            uint32_t off = (uint32_t)(rI[i] * LDSW + cI[i]) * 2;
            cpa16(st + off,        ap[i] + k0 + cI[i]);
            cpa16(st + ABUF + off, bp[i] + k0 + cI[i]);
        }
        cpa_commit();
    };

    float acc[4][4][4];
#pragma unroll
    for (int mi = 0; mi < 4; mi++)
#pragma unroll
        for (int ni = 0; ni < 4; ni++)
#pragma unroll
            for (int q = 0; q < 4; q++) acc[mi][ni][q] = 0.0f;

    const int NT = FFN_ / BK;   // 64
    load_tile(0, 0);
    load_tile(1, BK);
    load_tile(2, 2 * BK);

    int lr = lane >> 2;
    int lc = lane & 3;

    uint32_t a_loff = (uint32_t)((lane & 15) * ROWB + ((lane >> 4) & 1) * 16)
                    + (uint32_t)(wm * 64 * ROWB);
    uint32_t b_loff = (uint32_t)((((lane >> 4) & 1) * 8 + (lane & 7)) * ROWB
                    + ((lane >> 3) & 1) * 16)
                    + (uint32_t)(wn * 32 * ROWB);

    for (int kt = 0; kt < NT; kt++) {
        int buf = kt & (NSTG - 1);
        if (kt + 3 < NT)      { load_tile((kt + 3) & (NSTG - 1), (kt + 3) * BK); cpa_wait3(); }
        else if (kt + 2 < NT) { cpa_wait2(); }
        else if (kt + 1 < NT) { cpa_wait1(); }
        else                  { cpa_wait0(); }
        __syncthreads();

        uint32_t At = sbase + buf * STAGE;
        uint32_t Bt = At + ABUF;
#pragma unroll
        for (int s = 0; s < 2; s++) {
            uint32_t ks = s * 32;
            uint32_t a[4][4], b[4][2];
#pragma unroll
            for (int mi = 0; mi < 4; mi++)
                ldsm_x4(a[mi][0], a[mi][1], a[mi][2], a[mi][3],
                        At + (uint32_t)(mi * 16 * ROWB) + ks + a_loff);
#pragma unroll
            for (int nj = 0; nj < 2; nj++)
                ldsm_x4(b[2 * nj][0], b[2 * nj][1], b[2 * nj + 1][0], b[2 * nj + 1][1],
                        Bt + (uint32_t)(nj * 16 * ROWB) + ks + b_loff);
#pragma unroll
            for (int mi = 0; mi < 4; mi++)
#pragma unroll
                for (int ni = 0; ni < 4; ni++)
                    mma_f16(acc[mi][ni], a[mi], b[ni], acc[mi][ni]);
        }
        __syncthreads();
    }

    const float* b2 = w2b + (size_t)e * HID_;
#pragma unroll
    for (int mi = 0; mi < 4; mi++) {
        int r = row0 + wm * 64 + mi * 16 + lr;
#pragma unroll
        for (int ni = 0; ni < 4; ni++) {
            int c = nb + wn * 32 + ni * 8 + lc * 2;
            float b0 = b2[c], b1 = b2[c + 1];
            if (r < rowEnd) {
                int tok = g_tok[r]; float w = g_w[r];
                atomicAdd(&out[(size_t)tok * HID_ + c],     (acc[mi][ni][0] + b0) * w);
                atomicAdd(&out[(size_t)tok * HID_ + c + 1], (acc[mi][ni][1] + b1) * w);
            }
            if (r + 8 < rowEnd) {
                int tok = g_tok[r + 8]; float w = g_w[r + 8];
                atomicAdd(&out[(size_t)tok * HID_ + c],     (acc[mi][ni][2] + b0) * w);
                atomicAdd(&out[(size_t)tok * HID_ + c + 1], (acc[mi][ni][3] + b1) * w);
            }
        }
    }
}

// ---------------- launch ----------------
extern "C" void kernel_launch(void* const* d_in, const int* in_sizes, int n_in,
                              void* d_out, int out_size) {
    (void)in_sizes; (void)n_in; (void)out_size;
    const float* x   = (const float*)d_in[0];
    const float* rw  = (const float*)d_in[1];
    const float* rb  = (const float*)d_in[2];
    const float* w1  = (const float*)d_in[3];
    const float* w1b = (const float*)d_in[4];
    const float* w2  = (const float*)d_in[5];
    const float* w2b = (const float*)d_in[6];
    float* out = (float*)d_out;

    static cudaStream_t s2 = nullptr;
    static cudaEvent_t evFork = nullptr, evW1a = nullptr, evW1b = nullptr, evW2 = nullptr;
    if (!s2) {
        cudaStreamCreateWithFlags(&s2, cudaStreamNonBlocking);
        cudaEventCreateWithFlags(&evFork, cudaEventDisableTiming);
        cudaEventCreateWithFlags(&evW1a, cudaEventDisableTiming);
        cudaEventCreateWithFlags(&evW1b, cudaEventDisableTiming);
        cudaEventCreateWithFlags(&evW2,  cudaEventDisableTiming);
    }

    cudaFuncSetAttribute(k_gemm1, cudaFuncAttributeMaxDynamicSharedMemorySize, NSTG * STAGE);
    cudaFuncSetAttribute(k_gemm2, cudaFuncAttributeMaxDynamicSharedMemorySize, NSTG * STAGE);

    __half* w1h; cudaGetSymbolAddress((void**)&w1h, g_w1h);
    __half* w2h; cudaGetSymbolAddress((void**)&w2h, g_w2h);

    const int W1_HALF4 = (E_ * 2 * FFN_ * HID_) / 4 / 2;   // float4 count per half

    // fork: chunked w1 converts, then w2 convert + out zeroing, on s2
    cudaEventRecord(evFork, 0);
    cudaStreamWaitEvent(s2, evFork, 0);
    k_cvt_h<<<2048, 256, 0, s2>>>((const float4*)w1, (uint2*)w1h, W1_HALF4);
    cudaEventRecord(evW1a, s2);
    k_cvt_h<<<2048, 256, 0, s2>>>((const float4*)w1 + W1_HALF4, (uint2*)w1h + W1_HALF4, W1_HALF4);
    cudaEventRecord(evW1b, s2);
    k_cvt_h<<<2048, 256, 0, s2>>>((const float4*)w2, (uint2*)w2h, (E_ * HID_ * FFN_) / 4);
    k_zout<<<1024, 256, 0, s2>>>(out);
    cudaEventRecord(evW2, s2);

    // main: router(+x cvt), scan(+counter reset), place
    k_router<<<M_TOK / 8, 256>>>(x, rw, rb, out);
    k_scan<<<1, 32>>>();
    k_place<<<NSLOT / 256, 256>>>();

    // GEMM1 in two expert-halves, each gated only on its w1 chunk
    dim3 g1(FFN_ / 64, NSLOT / 128, E_ / 2);
    cudaStreamWaitEvent(0, evW1a, 0);
    k_gemm1<<<g1, 256, NSTG * STAGE>>>(w1b, 0);
    cudaStreamWaitEvent(0, evW1b, 0);
    k_gemm1<<<g1, 256, NSTG * STAGE>>>(w1b, E_ / 2);

    cudaStreamWaitEvent(0, evW2, 0);
    dim3 g2(HID_ / 128, NSLOT / 128, E_);
    k_gemm2<<<g2, 256, NSTG * STAGE>>>(w2b, out);
}

// round 14
// speedup vs baseline: 1.1239x; 1.1239x over previous
#include <cuda_runtime.h>
#include <cuda_fp16.h>
#include <cstdint>

#define E_       8
#define TOPK_    2
#define HID_     1024
#define FFN_     2048
#define M_TOK    2048
#define NSLOT    (M_TOK * TOPK_)      // 4096
#define OUT_MAIN (M_TOK * HID_)       // 2097152

#define BK    32
#define LDSW  40                      // smem row stride in halves (80B)
#define ROWB  80
#define ABUF  (128 * ROWB)            // 10240 B per operand tile
#define STAGE (2 * ABUF)              // 20480 B per stage (A + B)
#define NSTG  4

// ---------------- device scratch ----------------
__device__ int    g_cnt[E_];
__device__ int    g_off[E_ + 1];
__device__ int    g_cur[E_];
__device__ int    g_slot_e[NSLOT];
__device__ float  g_slot_w[NSLOT];
__device__ int    g_tok[NSLOT];
__device__ float  g_w[NSLOT];
__device__ __half g_hh[(size_t)NSLOT * FFN_];
__device__ __half g_xh[(size_t)M_TOK * HID_];
__device__ __half g_w1h[(size_t)E_ * 2 * FFN_ * HID_];
__device__ __half g_w2h[(size_t)E_ * HID_ * FFN_];

// ---------------- helpers ----------------
__device__ __forceinline__ void mma_f16(float* d, const uint32_t* a,
                                        const uint32_t* b, const float* c) {
    asm("mma.sync.aligned.m16n8k16.row.col.f32.f16.f16.f32 "
        "{%0,%1,%2,%3}, {%4,%5,%6,%7}, {%8,%9}, {%10,%11,%12,%13};\n"
        : "=f"(d[0]), "=f"(d[1]), "=f"(d[2]), "=f"(d[3])
        : "r"(a[0]), "r"(a[1]), "r"(a[2]), "r"(a[3]),
          "r"(b[0]), "r"(b[1]),
          "f"(c[0]), "f"(c[1]), "f"(c[2]), "f"(c[3]));
}
__device__ __forceinline__ void ldsm_x4(uint32_t& r0, uint32_t& r1,
                                        uint32_t& r2, uint32_t& r3, uint32_t addr) {
    asm volatile("ldmatrix.sync.aligned.m8n8.x4.shared.b16 {%0,%1,%2,%3}, [%4];"
                 : "=r"(r0), "=r"(r1), "=r"(r2), "=r"(r3) : "r"(addr));
}
__device__ __forceinline__ void cpa16(uint32_t saddr, const void* g) {
    asm volatile("cp.async.cg.shared.global [%0], [%1], 16;\n" :: "r"(saddr), "l"(g));
}
__device__ __forceinline__ void cpa_commit() { asm volatile("cp.async.commit_group;\n"); }
__device__ __forceinline__ void cpa_wait3()  { asm volatile("cp.async.wait_group 3;\n"); }
__device__ __forceinline__ void cpa_wait2()  { asm volatile("cp.async.wait_group 2;\n"); }
__device__ __forceinline__ void cpa_wait1()  { asm volatile("cp.async.wait_group 1;\n"); }
__device__ __forceinline__ void cpa_wait0()  { asm volatile("cp.async.wait_group 0;\n"); }
__device__ __forceinline__ uint32_t smem_u32(const void* p) {
    return (uint32_t)__cvta_generic_to_shared(p);
}

// ---------------- router (float4 loads) + fused x->fp16 ----------------
__global__ void k_router(const float* __restrict__ x,
                         const float* __restrict__ rw,
                         const float* __restrict__ rb,
                         float* __restrict__ out) {
    int warp = (blockIdx.x * blockDim.x + threadIdx.x) >> 5;
    int lane = threadIdx.x & 31;
    if (warp >= M_TOK) return;

    const float4* xr4 = (const float4*)(x + (size_t)warp * HID_);
    float4 xv[8];
#pragma unroll
    for (int j = 0; j < 8; j++) xv[j] = xr4[lane + 32 * j];

    // fused fp16 copy of x
    uint2* xh2 = (uint2*)(g_xh + (size_t)warp * HID_);
#pragma unroll
    for (int j = 0; j < 8; j++) {
        __half2 lo = __floats2half2_rn(xv[j].x, xv[j].y);
        __half2 hi = __floats2half2_rn(xv[j].z, xv[j].w);
        uint2 o; o.x = *(uint32_t*)&lo; o.y = *(uint32_t*)&hi;
        xh2[lane + 32 * j] = o;
    }

    float logits[E_];
#pragma unroll
    for (int e = 0; e < E_; e++) {
        const float4* w4 = (const float4*)(rw + (size_t)e * HID_);
        float acc = 0.0f;
#pragma unroll
        for (int j = 0; j < 8; j++) {
            float4 w = w4[lane + 32 * j];
            acc += xv[j].x * w.x + xv[j].y * w.y + xv[j].z * w.z + xv[j].w * w.w;
        }
#pragma unroll
        for (int o = 16; o > 0; o >>= 1) acc += __shfl_xor_sync(0xffffffffu, acc, o);
        logits[e] = acc + rb[e];
    }

    if (lane == 0) {
        float mx = logits[0];
#pragma unroll
        for (int e = 1; e < E_; e++) mx = fmaxf(mx, logits[e]);
        float p[E_], s = 0.0f;
#pragma unroll
        for (int e = 0; e < E_; e++) { p[e] = expf(logits[e] - mx); s += p[e]; }
        float inv = 1.0f / s;
#pragma unroll
        for (int e = 0; e < E_; e++) p[e] *= inv;

        int i0 = 0;
#pragma unroll
        for (int e = 1; e < E_; e++) if (p[e] > p[i0]) i0 = e;
        int i1 = -1;
#pragma unroll
        for (int e = 0; e < E_; e++) {
            if (e == i0) continue;
            if (i1 < 0 || p[e] > p[i1]) i1 = e;
        }

        out[OUT_MAIN + warp * 2 + 0] = p[i0];
        out[OUT_MAIN + warp * 2 + 1] = p[i1];
        g_slot_e[warp * 2 + 0] = i0;  g_slot_w[warp * 2 + 0] = p[i0];
        g_slot_e[warp * 2 + 1] = i1;  g_slot_w[warp * 2 + 1] = p[i1];
        atomicAdd(&g_cnt[i0], 1);
        atomicAdd(&g_cnt[i1], 1);
    }
}

// scan: compute offsets, reset counters for next replay
__global__ void k_scan() {
    if (threadIdx.x == 0) {
        int s = 0;
        for (int e = 0; e < E_; e++) { g_off[e] = s; g_cur[e] = s; s += g_cnt[e]; g_cnt[e] = 0; }
        g_off[E_] = s;
    }
}

__global__ void k_place() {
    int s = blockIdx.x * blockDim.x + threadIdx.x;
    if (s >= NSLOT) return;
    int e = g_slot_e[s];
    int p = atomicAdd(&g_cur[e], 1);
    g_tok[p] = s >> 1;
    g_w[p]   = g_slot_w[s];
}

// fp32 -> fp16 streaming convert (RN)
__global__ void k_cvt_h(const float4* __restrict__ src, uint2* __restrict__ dst, int n4) {
    int i = blockIdx.x * blockDim.x + threadIdx.x;
    int stride = gridDim.x * blockDim.x;
    for (; i < n4; i += stride) {
        float4 v = src[i];
        __half2 lo = __floats2half2_rn(v.x, v.y);
        __half2 hi = __floats2half2_rn(v.z, v.w);
        uint2 o;
        o.x = *(uint32_t*)&lo;
        o.y = *(uint32_t*)&hi;
        dst[i] = o;
    }
}

// zero out region (runs on s2)
__global__ void k_zout(float* __restrict__ out) {
    int i = blockIdx.x * blockDim.x + threadIdx.x;
    for (int j = i; j < OUT_MAIN; j += gridDim.x * blockDim.x) out[j] = 0.0f;
}

// ============================================================================
// GEMM1 (fp16 HMMA + ldmatrix): h = silu(x@Wg^T + bg) * (x@Wu^T + bu)
// Block 128 slot rows x 64 h-cols, 256 threads (8 warps 2x4, warp 64x32).
// ============================================================================
__global__ void __launch_bounds__(256, 2)
k_gemm1(const float* __restrict__ w1b) {
    int e = blockIdx.z;
    int rowEnd = g_off[e + 1];
    int row0 = g_off[e] + blockIdx.y * 128;
    if (row0 >= rowEnd) return;
    int nb = blockIdx.x * 64;

    extern __shared__ __half dsm[];
    __shared__ const __half* s_aptr[128];

    int tid  = threadIdx.x;
    int lane = tid & 31;
    int wid  = tid >> 5;
    int wm   = wid >> 2;
    int wn   = wid & 3;
    uint32_t sbase = smem_u32(dsm);

    for (int r = tid; r < 128; r += 256) {
        int gr = row0 + r;
        if (gr >= rowEnd) gr = rowEnd - 1;
        s_aptr[r] = g_xh + (size_t)g_tok[gr] * HID_;
    }
    __syncthreads();

    int rI[2], cI[2];
    const __half* bp[2];
#pragma unroll
    for (int i = 0; i < 2; i++) {
        int idx = tid + 256 * i;
        rI[i] = idx >> 2;
        cI[i] = (idx & 3) * 8;
        int r = rI[i];
        size_t wrow = (size_t)e * 2 * FFN_ + ((r & 1) ? (FFN_ + nb + (r >> 1)) : (nb + (r >> 1)));
        bp[i] = g_w1h + wrow * HID_;
    }

    auto load_tile = [&](int s, int k0) {
        uint32_t st = sbase + s * STAGE;
#pragma unroll
        for (int i = 0; i < 2; i++) {
            uint32_t off = (uint32_t)(rI[i] * LDSW + cI[i]) * 2;
            cpa16(st + off,        s_aptr[rI[i]] + k0 + cI[i]);
            cpa16(st + ABUF + off, bp[i] + k0 + cI[i]);
        }
        cpa_commit();
    };

    float acc[4][4][4];
#pragma unroll
    for (int mi = 0; mi < 4; mi++)
#pragma unroll
        for (int ni = 0; ni < 4; ni++)
#pragma unroll
            for (int q = 0; q < 4; q++) acc[mi][ni][q] = 0.0f;

    const int NT = HID_ / BK;   // 32
    load_tile(0, 0);
    load_tile(1, BK);
    load_tile(2, 2 * BK);

    int lr = lane >> 2;
    int lc = lane & 3;

    uint32_t a_loff = (uint32_t)((lane & 15) * ROWB + ((lane >> 4) & 1) * 16)
                    + (uint32_t)(wm * 64 * ROWB);
    uint32_t b_loff = (uint32_t)((((lane >> 4) & 1) * 8 + (lane & 7)) * ROWB
                    + ((lane >> 3) & 1) * 16)
                    + (uint32_t)(wn * 32 * ROWB);

    for (int kt = 0; kt < NT; kt++) {
        int buf = kt & (NSTG - 1);
        if (kt + 3 < NT)      { load_tile((kt + 3) & (NSTG - 1), (kt + 3) * BK); cpa_wait3(); }
        else if (kt + 2 < NT) { cpa_wait2(); }
        else if (kt + 1 < NT) { cpa_wait1(); }
        else                  { cpa_wait0(); }
        __syncthreads();

        uint32_t At = sbase + buf * STAGE;
        uint32_t Bt = At + ABUF;
#pragma unroll
        for (int s = 0; s < 2; s++) {
            uint32_t ks = s * 32;
            uint32_t a[4][4], b[4][2];
#pragma unroll
            for (int mi = 0; mi < 4; mi++)
                ldsm_x4(a[mi][0], a[mi][1], a[mi][2], a[mi][3],
                        At + (uint32_t)(mi * 16 * ROWB) + ks + a_loff);
#pragma unroll
            for (int nj = 0; nj < 2; nj++)
                ldsm_x4(b[2 * nj][0], b[2 * nj][1], b[2 * nj + 1][0], b[2 * nj + 1][1],
                        Bt + (uint32_t)(nj * 16 * ROWB) + ks + b_loff);
#pragma unroll
            for (int mi = 0; mi < 4; mi++)
#pragma unroll
                for (int ni = 0; ni < 4; ni++)
                    mma_f16(acc[mi][ni], a[mi], b[ni], acc[mi][ni]);
        }
        __syncthreads();
    }

    const float* bg_base = w1b + (size_t)e * 2 * FFN_;
    const float* bu_base = bg_base + FFN_;
#pragma unroll
    for (int mi = 0; mi < 4; mi++) {
        int r = row0 + wm * 64 + mi * 16 + lr;
#pragma unroll
        for (int ni = 0; ni < 4; ni++) {
            int gj = nb + wn * 16 + ni * 4 + lc;
            float bg = bg_base[gj];
            float bu = bu_base[gj];
            if (r < rowEnd) {
                float g = acc[mi][ni][0] + bg;
                float u = acc[mi][ni][1] + bu;
                g_hh[(size_t)r * FFN_ + gj] = __float2half_rn((g / (1.0f + expf(-g))) * u);
            }
            if (r + 8 < rowEnd) {
                float g = acc[mi][ni][2] + bg;
                float u = acc[mi][ni][3] + bu;
                g_hh[(size_t)(r + 8) * FFN_ + gj] = __float2half_rn((g / (1.0f + expf(-g))) * u);
            }
        }
    }
}

// ============================================================================
// GEMM2 (fp16 HMMA + ldmatrix): out[tok] += w * (h@W2^T + b2)
// ============================================================================
__global__ void __launch_bounds__(256, 2)
k_gemm2(const float* __restrict__ w2b, float* __restrict__ out) {
    int e = blockIdx.z;
    int rowEnd = g_off[e + 1];
    int row0 = g_off[e] + blockIdx.y * 128;
    if (row0 >= rowEnd) return;
    int nb = blockIdx.x * 128;

    extern __shared__ __half dsm[];

    int tid  = threadIdx.x;
    int lane = tid & 31;
    int wid  = tid >> 5;
    int wm   = wid >> 2;
    int wn   = wid & 3;
    uint32_t sbase = smem_u32(dsm);

    int rI[2], cI[2];
    const __half* ap[2];
    const __half* bp[2];
#pragma unroll
    for (int i = 0; i < 2; i++) {
        int idx = tid + 256 * i;
        rI[i] = idx >> 2;
        cI[i] = (idx & 3) * 8;
        int gr = row0 + rI[i];
        if (gr >= rowEnd) gr = rowEnd - 1;
        ap[i] = g_hh + (size_t)gr * FFN_;
        bp[i] = g_w2h + ((size_t)e * HID_ + (nb + rI[i])) * FFN_;
    }

    auto load_tile = [&](int s, int k0) {
        uint32_t st = sbase + s * STAGE;
#pragma unroll
        for (int i = 0; i < 2; i++) {
            uint32_t off = (uint32_t)(rI[i] * LDSW + cI[i]) * 2;
            cpa16(st + off,        ap[i] + k0 + cI[i]);
            cpa16(st + ABUF + off, bp[i] + k0 + cI[i]);
        }
        cpa_commit();
    };

    float acc[4][4][4];
#pragma unroll
    for (int mi = 0; mi < 4; mi++)
#pragma unroll
        for (int ni = 0; ni < 4; ni++)
#pragma unroll
            for (int q = 0; q < 4; q++) acc[mi][ni][q] = 0.0f;

    const int NT = FFN_ / BK;   // 64
    load_tile(0, 0);
    load_tile(1, BK);
    load_tile(2, 2 * BK);

    int lr = lane >> 2;
    int lc = lane & 3;

    uint32_t a_loff = (uint32_t)((lane & 15) * ROWB + ((lane >> 4) & 1) * 16)
                    + (uint32_t)(wm * 64 * ROWB);
    uint32_t b_loff = (uint32_t)((((lane >> 4) & 1) * 8 + (lane & 7)) * ROWB
                    + ((lane >> 3) & 1) * 16)
                    + (uint32_t)(wn * 32 * ROWB);

    for (int kt = 0; kt < NT; kt++) {
        int buf = kt & (NSTG - 1);
        if (kt + 3 < NT)      { load_tile((kt + 3) & (NSTG - 1), (kt + 3) * BK); cpa_wait3(); }
        else if (kt + 2 < NT) { cpa_wait2(); }
        else if (kt + 1 < NT) { cpa_wait1(); }
        else                  { cpa_wait0(); }
        __syncthreads();

        uint32_t At = sbase + buf * STAGE;
        uint32_t Bt = At + ABUF;
#pragma unroll
        for (int s = 0; s < 2; s++) {
            uint32_t ks = s * 32;
            uint32_t a[4][4], b[4][2];
#pragma unroll
            for (int mi = 0; mi < 4; mi++)
                ldsm_x4(a[mi][0], a[mi][1], a[mi][2], a[mi][3],
                        At + (uint32_t)(mi * 16 * ROWB) + ks + a_loff);
#pragma unroll
            for (int nj = 0; nj < 2; nj++)
                ldsm_x4(b[2 * nj][0], b[2 * nj][1], b[2 * nj + 1][0], b[2 * nj + 1][1],
                        Bt + (uint32_t)(nj * 16 * ROWB) + ks + b_loff);
#pragma unroll
            for (int mi = 0; mi < 4; mi++)
#pragma unroll
                for (int ni = 0; ni < 4; ni++)
                    mma_f16(acc[mi][ni], a[mi], b[ni], acc[mi][ni]);
        }
        __syncthreads();
    }

    const float* b2 = w2b + (size_t)e * HID_;
#pragma unroll
    for (int mi = 0; mi < 4; mi++) {
        int r = row0 + wm * 64 + mi * 16 + lr;
#pragma unroll
        for (int ni = 0; ni < 4; ni++) {
            int c = nb + wn * 32 + ni * 8 + lc * 2;
            float b0 = b2[c], b1 = b2[c + 1];
            if (r < rowEnd) {
                int tok = g_tok[r]; float w = g_w[r];
                atomicAdd(&out[(size_t)tok * HID_ + c],     (acc[mi][ni][0] + b0) * w);
                atomicAdd(&out[(size_t)tok * HID_ + c + 1], (acc[mi][ni][1] + b1) * w);
            }
            if (r + 8 < rowEnd) {
                int tok = g_tok[r + 8]; float w = g_w[r + 8];
                atomicAdd(&out[(size_t)tok * HID_ + c],     (acc[mi][ni][2] + b0) * w);
                atomicAdd(&out[(size_t)tok * HID_ + c + 1], (acc[mi][ni][3] + b1) * w);
            }
        }
    }
}

// ---------------- launch ----------------
extern "C" void kernel_launch(void* const* d_in, const int* in_sizes, int n_in,
                              void* d_out, int out_size) {
    (void)in_sizes; (void)n_in; (void)out_size;
    const float* x   = (const float*)d_in[0];
    const float* rw  = (const float*)d_in[1];
    const float* rb  = (const float*)d_in[2];
    const float* w1  = (const float*)d_in[3];
    const float* w1b = (const float*)d_in[4];
    const float* w2  = (const float*)d_in[5];
    const float* w2b = (const float*)d_in[6];
    float* out = (float*)d_out;

    static cudaStream_t s2 = nullptr;
    static cudaEvent_t evFork = nullptr, evW1 = nullptr, evW2 = nullptr;
    if (!s2) {
        cudaStreamCreateWithFlags(&s2, cudaStreamNonBlocking);
        cudaEventCreateWithFlags(&evFork, cudaEventDisableTiming);
        cudaEventCreateWithFlags(&evW1,  cudaEventDisableTiming);
        cudaEventCreateWithFlags(&evW2,  cudaEventDisableTiming);
    }

    cudaFuncSetAttribute(k_gemm1, cudaFuncAttributeMaxDynamicSharedMemorySize, NSTG * STAGE);
    cudaFuncSetAttribute(k_gemm2, cudaFuncAttributeMaxDynamicSharedMemorySize, NSTG * STAGE);

    __half* w1h; cudaGetSymbolAddress((void**)&w1h, g_w1h);
    __half* w2h; cudaGetSymbolAddress((void**)&w2h, g_w2h);

    // fork: w1 convert (evW1), then w2 convert + out zeroing (evW2), on s2
    cudaEventRecord(evFork, 0);
    cudaStreamWaitEvent(s2, evFork, 0);
    k_cvt_h<<<2048, 256, 0, s2>>>((const float4*)w1, (uint2*)w1h, (E_ * 2 * FFN_ * HID_) / 4);
    cudaEventRecord(evW1, s2);
    k_cvt_h<<<2048, 256, 0, s2>>>((const float4*)w2, (uint2*)w2h, (E_ * HID_ * FFN_) / 4);
    k_zout<<<1024, 256, 0, s2>>>(out);
    cudaEventRecord(evW2, s2);

    // main: router(+x cvt), scan(+counter reset), place
    k_router<<<M_TOK / 8, 256>>>(x, rw, rb, out);
    k_scan<<<1, 32>>>();
    k_place<<<NSLOT / 256, 256>>>();

    // join: GEMM1 needs w1h; GEMM2 needs w2h + zeroed out
    cudaStreamWaitEvent(0, evW1, 0);
    dim3 g1(FFN_ / 64, NSLOT / 128, E_);
    k_gemm1<<<g1, 256, NSTG * STAGE>>>(w1b);

    cudaStreamWaitEvent(0, evW2, 0);
    dim3 g2(HID_ / 128, NSLOT / 128, E_);
    k_gemm2<<<g2, 256, NSTG * STAGE>>>(w2b, out);
}

// round 15
// speedup vs baseline: 1.1294x; 1.0049x over previous
#include <cuda_runtime.h>
#include <cuda_fp16.h>
#include <cstdint>

#define E_       8
#define TOPK_    2
#define HID_     1024
#define FFN_     2048
#define M_TOK    2048
#define NSLOT    (M_TOK * TOPK_)      // 4096
#define OUT_MAIN (M_TOK * HID_)       // 2097152

#define BK    32
#define LDSW  40                      // smem row stride in halves (80B)
#define ROWB  80
#define ABUF  (128 * ROWB)            // 10240 B per operand tile
#define STAGE (2 * ABUF)              // 20480 B per stage (A + B)
#define NSTG  4

// ---------------- device scratch ----------------
__device__ int    g_cnt[E_];
__device__ int    g_off[E_ + 1];
__device__ int    g_cur[E_];
__device__ int    g_slot_e[NSLOT];
__device__ float  g_slot_w[NSLOT];
__device__ int    g_tok[NSLOT];
__device__ float  g_w[NSLOT];
__device__ int    g_pos[NSLOT];                         // slot -> grouped position
__device__ float  g_part[(size_t)NSLOT * HID_];         // 16 MB per-slot partials
__device__ __half g_hh[(size_t)NSLOT * FFN_];
__device__ __half g_xh[(size_t)M_TOK * HID_];
__device__ __half g_w1h[(size_t)E_ * 2 * FFN_ * HID_];
__device__ __half g_w2h[(size_t)E_ * HID_ * FFN_];

// ---------------- helpers ----------------
__device__ __forceinline__ void mma_f16(float* d, const uint32_t* a,
                                        const uint32_t* b, const float* c) {
    asm("mma.sync.aligned.m16n8k16.row.col.f32.f16.f16.f32 "
        "{%0,%1,%2,%3}, {%4,%5,%6,%7}, {%8,%9}, {%10,%11,%12,%13};\n"
        : "=f"(d[0]), "=f"(d[1]), "=f"(d[2]), "=f"(d[3])
        : "r"(a[0]), "r"(a[1]), "r"(a[2]), "r"(a[3]),
          "r"(b[0]), "r"(b[1]),
          "f"(c[0]), "f"(c[1]), "f"(c[2]), "f"(c[3]));
}
__device__ __forceinline__ void ldsm_x4(uint32_t& r0, uint32_t& r1,
                                        uint32_t& r2, uint32_t& r3, uint32_t addr) {
    asm volatile("ldmatrix.sync.aligned.m8n8.x4.shared.b16 {%0,%1,%2,%3}, [%4];"
                 : "=r"(r0), "=r"(r1), "=r"(r2), "=r"(r3) : "r"(addr));
}
__device__ __forceinline__ void cpa16(uint32_t saddr, const void* g) {
    asm volatile("cp.async.cg.shared.global [%0], [%1], 16;\n" :: "r"(saddr), "l"(g));
}
__device__ __forceinline__ void cpa_commit() { asm volatile("cp.async.commit_group;\n"); }
__device__ __forceinline__ void cpa_wait3()  { asm volatile("cp.async.wait_group 3;\n"); }
__device__ __forceinline__ void cpa_wait2()  { asm volatile("cp.async.wait_group 2;\n"); }
__device__ __forceinline__ void cpa_wait1()  { asm volatile("cp.async.wait_group 1;\n"); }
__device__ __forceinline__ void cpa_wait0()  { asm volatile("cp.async.wait_group 0;\n"); }
__device__ __forceinline__ uint32_t smem_u32(const void* p) {
    return (uint32_t)__cvta_generic_to_shared(p);
}

// ---------------- router (float4 loads) + fused x->fp16 ----------------
__global__ void k_router(const float* __restrict__ x,
                         const float* __restrict__ rw,
                         const float* __restrict__ rb,
                         float* __restrict__ out) {
    int warp = (blockIdx.x * blockDim.x + threadIdx.x) >> 5;
    int lane = threadIdx.x & 31;
    if (warp >= M_TOK) return;

    const float4* xr4 = (const float4*)(x + (size_t)warp * HID_);
    float4 xv[8];
#pragma unroll
    for (int j = 0; j < 8; j++) xv[j] = xr4[lane + 32 * j];

    // fused fp16 copy of x
    uint2* xh2 = (uint2*)(g_xh + (size_t)warp * HID_);
#pragma unroll
    for (int j = 0; j < 8; j++) {
        __half2 lo = __floats2half2_rn(xv[j].x, xv[j].y);
        __half2 hi = __floats2half2_rn(xv[j].z, xv[j].w);
        uint2 o; o.x = *(uint32_t*)&lo; o.y = *(uint32_t*)&hi;
        xh2[lane + 32 * j] = o;
    }

    float logits[E_];
#pragma unroll
    for (int e = 0; e < E_; e++) {
        const float4* w4 = (const float4*)(rw + (size_t)e * HID_);
        float acc = 0.0f;
#pragma unroll
        for (int j = 0; j < 8; j++) {
            float4 w = w4[lane + 32 * j];
            acc += xv[j].x * w.x + xv[j].y * w.y + xv[j].z * w.z + xv[j].w * w.w;
        }
#pragma unroll
        for (int o = 16; o > 0; o >>= 1) acc += __shfl_xor_sync(0xffffffffu, acc, o);
        logits[e] = acc + rb[e];
    }

    if (lane == 0) {
        float mx = logits[0];
#pragma unroll
        for (int e = 1; e < E_; e++) mx = fmaxf(mx, logits[e]);
        float p[E_], s = 0.0f;
#pragma unroll
        for (int e = 0; e < E_; e++) { p[e] = expf(logits[e] - mx); s += p[e]; }
        float inv = 1.0f / s;
#pragma unroll
        for (int e = 0; e < E_; e++) p[e] *= inv;

        int i0 = 0;
#pragma unroll
        for (int e = 1; e < E_; e++) if (p[e] > p[i0]) i0 = e;
        int i1 = -1;
#pragma unroll
        for (int e = 0; e < E_; e++) {
            if (e == i0) continue;
            if (i1 < 0 || p[e] > p[i1]) i1 = e;
        }

        out[OUT_MAIN + warp * 2 + 0] = p[i0];
        out[OUT_MAIN + warp * 2 + 1] = p[i1];
        g_slot_e[warp * 2 + 0] = i0;  g_slot_w[warp * 2 + 0] = p[i0];
        g_slot_e[warp * 2 + 1] = i1;  g_slot_w[warp * 2 + 1] = p[i1];
        atomicAdd(&g_cnt[i0], 1);
        atomicAdd(&g_cnt[i1], 1);
    }
}

// scan: compute offsets, reset counters for next replay
__global__ void k_scan() {
    if (threadIdx.x == 0) {
        int s = 0;
        for (int e = 0; e < E_; e++) { g_off[e] = s; g_cur[e] = s; s += g_cnt[e]; g_cnt[e] = 0; }
        g_off[E_] = s;
    }
}

__global__ void k_place() {
    int s = blockIdx.x * blockDim.x + threadIdx.x;
    if (s >= NSLOT) return;
    int e = g_slot_e[s];
    int p = atomicAdd(&g_cur[e], 1);
    g_tok[p] = s >> 1;
    g_w[p]   = g_slot_w[s];
    g_pos[s] = p;
}

// fp32 -> fp16 streaming convert (RN)
__global__ void k_cvt_h(const float4* __restrict__ src, uint2* __restrict__ dst, int n4) {
    int i = blockIdx.x * blockDim.x + threadIdx.x;
    int stride = gridDim.x * blockDim.x;
    for (; i < n4; i += stride) {
        float4 v = src[i];
        __half2 lo = __floats2half2_rn(v.x, v.y);
        __half2 hi = __floats2half2_rn(v.z, v.w);
        uint2 o;
        o.x = *(uint32_t*)&lo;
        o.y = *(uint32_t*)&hi;
        dst[i] = o;
    }
}

// combine: out[t] = part[pos(2t)] + part[pos(2t+1)]  (float4, fully coalesced)
__global__ void k_combine(float* __restrict__ out) {
    int idx = blockIdx.x * blockDim.x + threadIdx.x;     // 0 .. M_TOK*HID/4-1
    int t = idx >> 8;                                    // token (HID/4 = 256 chunks)
    int j = idx & 255;
    const float4* p0 = (const float4*)(g_part + (size_t)g_pos[2 * t] * HID_);
    const float4* p1 = (const float4*)(g_part + (size_t)g_pos[2 * t + 1] * HID_);
    float4 a = p0[j], b = p1[j];
    float4 r;
    r.x = a.x + b.x; r.y = a.y + b.y; r.z = a.z + b.z; r.w = a.w + b.w;
    ((float4*)out)[idx] = r;
}

// ============================================================================
// GEMM1 (fp16 HMMA + ldmatrix): h = silu(x@Wg^T + bg) * (x@Wu^T + bu)
// ============================================================================
__global__ void __launch_bounds__(256, 2)
k_gemm1(const float* __restrict__ w1b) {
    int e = blockIdx.z;
    int rowEnd = g_off[e + 1];
    int row0 = g_off[e] + blockIdx.y * 128;
    if (row0 >= rowEnd) return;
    int nb = blockIdx.x * 64;

    extern __shared__ __half dsm[];
    __shared__ const __half* s_aptr[128];

    int tid  = threadIdx.x;
    int lane = tid & 31;
    int wid  = tid >> 5;
    int wm   = wid >> 2;
    int wn   = wid & 3;
    uint32_t sbase = smem_u32(dsm);

    for (int r = tid; r < 128; r += 256) {
        int gr = row0 + r;
        if (gr >= rowEnd) gr = rowEnd - 1;
        s_aptr[r] = g_xh + (size_t)g_tok[gr] * HID_;
    }
    __syncthreads();

    int rI[2], cI[2];
    const __half* bp[2];
#pragma unroll
    for (int i = 0; i < 2; i++) {
        int idx = tid + 256 * i;
        rI[i] = idx >> 2;
        cI[i] = (idx & 3) * 8;
        int r = rI[i];
        size_t wrow = (size_t)e * 2 * FFN_ + ((r & 1) ? (FFN_ + nb + (r >> 1)) : (nb + (r >> 1)));
        bp[i] = g_w1h + wrow * HID_;
    }

    auto load_tile = [&](int s, int k0) {
        uint32_t st = sbase + s * STAGE;
#pragma unroll
        for (int i = 0; i < 2; i++) {
            uint32_t off = (uint32_t)(rI[i] * LDSW + cI[i]) * 2;
            cpa16(st + off,        s_aptr[rI[i]] + k0 + cI[i]);
            cpa16(st + ABUF + off, bp[i] + k0 + cI[i]);
        }
        cpa_commit();
    };

    float acc[4][4][4];
#pragma unroll
    for (int mi = 0; mi < 4; mi++)
#pragma unroll
        for (int ni = 0; ni < 4; ni++)
#pragma unroll
            for (int q = 0; q < 4; q++) acc[mi][ni][q] = 0.0f;

    const int NT = HID_ / BK;   // 32
    load_tile(0, 0);
    load_tile(1, BK);
    load_tile(2, 2 * BK);

    int lr = lane >> 2;
    int lc = lane & 3;

    uint32_t a_loff = (uint32_t)((lane & 15) * ROWB + ((lane >> 4) & 1) * 16)
                    + (uint32_t)(wm * 64 * ROWB);
    uint32_t b_loff = (uint32_t)((((lane >> 4) & 1) * 8 + (lane & 7)) * ROWB
                    + ((lane >> 3) & 1) * 16)
                    + (uint32_t)(wn * 32 * ROWB);

    for (int kt = 0; kt < NT; kt++) {
        int buf = kt & (NSTG - 1);
        if (kt + 3 < NT)      { load_tile((kt + 3) & (NSTG - 1), (kt + 3) * BK); cpa_wait3(); }
        else if (kt + 2 < NT) { cpa_wait2(); }
        else if (kt + 1 < NT) { cpa_wait1(); }
        else                  { cpa_wait0(); }
        __syncthreads();

        uint32_t At = sbase + buf * STAGE;
        uint32_t Bt = At + ABUF;
#pragma unroll
        for (int s = 0; s < 2; s++) {
            uint32_t ks = s * 32;
            uint32_t a[4][4], b[4][2];
#pragma unroll
            for (int mi = 0; mi < 4; mi++)
                ldsm_x4(a[mi][0], a[mi][1], a[mi][2], a[mi][3],
                        At + (uint32_t)(mi * 16 * ROWB) + ks + a_loff);
#pragma unroll
            for (int nj = 0; nj < 2; nj++)
                ldsm_x4(b[2 * nj][0], b[2 * nj][1], b[2 * nj + 1][0], b[2 * nj + 1][1],
                        Bt + (uint32_t)(nj * 16 * ROWB) + ks + b_loff);
#pragma unroll
            for (int mi = 0; mi < 4; mi++)
#pragma unroll
                for (int ni = 0; ni < 4; ni++)
                    mma_f16(acc[mi][ni], a[mi], b[ni], acc[mi][ni]);
        }
        __syncthreads();
    }

    const float* bg_base = w1b + (size_t)e * 2 * FFN_;
    const float* bu_base = bg_base + FFN_;
#pragma unroll
    for (int mi = 0; mi < 4; mi++) {
        int r = row0 + wm * 64 + mi * 16 + lr;
#pragma unroll
        for (int ni = 0; ni < 4; ni++) {
            int gj = nb + wn * 16 + ni * 4 + lc;
            float bg = bg_base[gj];
            float bu = bu_base[gj];
            if (r < rowEnd) {
                float g = acc[mi][ni][0] + bg;
                float u = acc[mi][ni][1] + bu;
                g_hh[(size_t)r * FFN_ + gj] = __float2half_rn((g / (1.0f + expf(-g))) * u);
            }
            if (r + 8 < rowEnd) {
                float g = acc[mi][ni][2] + bg;
                float u = acc[mi][ni][3] + bu;
                g_hh[(size_t)(r + 8) * FFN_ + gj] = __float2half_rn((g / (1.0f + expf(-g))) * u);
            }
        }
    }
}

// ============================================================================
// GEMM2 (fp16 HMMA + ldmatrix): part[r] = (h@W2^T + b2) * w   (plain stores)
// ============================================================================
__global__ void __launch_bounds__(256, 2)
k_gemm2(const float* __restrict__ w2b) {
    int e = blockIdx.z;
    int rowEnd = g_off[e + 1];
    int row0 = g_off[e] + blockIdx.y * 128;
    if (row0 >= rowEnd) return;
    int nb = blockIdx.x * 128;

    extern __shared__ __half dsm[];

    int tid  = threadIdx.x;
    int lane = tid & 31;
    int wid  = tid >> 5;
    int wm   = wid >> 2;
    int wn   = wid & 3;
    uint32_t sbase = smem_u32(dsm);

    int rI[2], cI[2];
    const __half* ap[2];
    const __half* bp[2];
#pragma unroll
    for (int i = 0; i < 2; i++) {
        int idx = tid + 256 * i;
        rI[i] = idx >> 2;
        cI[i] = (idx & 3) * 8;
        int gr = row0 + rI[i];
        if (gr >= rowEnd) gr = rowEnd - 1;
        ap[i] = g_hh + (size_t)gr * FFN_;
        bp[i] = g_w2h + ((size_t)e * HID_ + (nb + rI[i])) * FFN_;
    }

    auto load_tile = [&](int s, int k0) {
        uint32_t st = sbase + s * STAGE;
#pragma unroll
        for (int i = 0; i < 2; i++) {
            uint32_t off = (uint32_t)(rI[i] * LDSW + cI[i]) * 2;
            cpa16(st + off,        ap[i] + k0 + cI[i]);
            cpa16(st + ABUF + off, bp[i] + k0 + cI[i]);
        }
        cpa_commit();
    };

    float acc[4][4][4];
#pragma unroll
    for (int mi = 0; mi < 4; mi++)
#pragma unroll
        for (int ni = 0; ni < 4; ni++)
#pragma unroll
            for (int q = 0; q < 4; q++) acc[mi][ni][q] = 0.0f;

    const int NT = FFN_ / BK;   // 64
    load_tile(0, 0);
    load_tile(1, BK);
    load_tile(2, 2 * BK);

    int lr = lane >> 2;
    int lc = lane & 3;

    uint32_t a_loff = (uint32_t)((lane & 15) * ROWB + ((lane >> 4) & 1) * 16)
                    + (uint32_t)(wm * 64 * ROWB);
    uint32_t b_loff = (uint32_t)((((lane >> 4) & 1) * 8 + (lane & 7)) * ROWB
                    + ((lane >> 3) & 1) * 16)
                    + (uint32_t)(wn * 32 * ROWB);

    for (int kt = 0; kt < NT; kt++) {
        int buf = kt & (NSTG - 1);
        if (kt + 3 < NT)      { load_tile((kt + 3) & (NSTG - 1), (kt + 3) * BK); cpa_wait3(); }
        else if (kt + 2 < NT) { cpa_wait2(); }
        else if (kt + 1 < NT) { cpa_wait1(); }
        else                  { cpa_wait0(); }
        __syncthreads();

        uint32_t At = sbase + buf * STAGE;
        uint32_t Bt = At + ABUF;
#pragma unroll
        for (int s = 0; s < 2; s++) {
            uint32_t ks = s * 32;
            uint32_t a[4][4], b[4][2];
#pragma unroll
            for (int mi = 0; mi < 4; mi++)
                ldsm_x4(a[mi][0], a[mi][1], a[mi][2], a[mi][3],
                        At + (uint32_t)(mi * 16 * ROWB) + ks + a_loff);
#pragma unroll
            for (int nj = 0; nj < 2; nj++)
                ldsm_x4(b[2 * nj][0], b[2 * nj][1], b[2 * nj + 1][0], b[2 * nj + 1][1],
                        Bt + (uint32_t)(nj * 16 * ROWB) + ks + b_loff);
#pragma unroll
            for (int mi = 0; mi < 4; mi++)
#pragma unroll
                for (int ni = 0; ni < 4; ni++)
                    mma_f16(acc[mi][ni], a[mi], b[ni], acc[mi][ni]);
        }
        __syncthreads();
    }

    const float* b2 = w2b + (size_t)e * HID_;
#pragma unroll
    for (int mi = 0; mi < 4; mi++) {
        int r = row0 + wm * 64 + mi * 16 + lr;
#pragma unroll
        for (int ni = 0; ni < 4; ni++) {
            int c = nb + wn * 32 + ni * 8 + lc * 2;
            float b0 = b2[c], b1 = b2[c + 1];
            if (r < rowEnd) {
                float w = g_w[r];
                float2 v = make_float2((acc[mi][ni][0] + b0) * w,
                                       (acc[mi][ni][1] + b1) * w);
                *(float2*)(g_part + (size_t)r * HID_ + c) = v;
            }
            if (r + 8 < rowEnd) {
                float w = g_w[r + 8];
                float2 v = make_float2((acc[mi][ni][2] + b0) * w,
                                       (acc[mi][ni][3] + b1) * w);
                *(float2*)(g_part + (size_t)(r + 8) * HID_ + c) = v;
            }
        }
    }
}

// ---------------- launch ----------------
extern "C" void kernel_launch(void* const* d_in, const int* in_sizes, int n_in,
                              void* d_out, int out_size) {
    (void)in_sizes; (void)n_in; (void)out_size;
    const float* x   = (const float*)d_in[0];
    const float* rw  = (const float*)d_in[1];
    const float* rb  = (const float*)d_in[2];
    const float* w1  = (const float*)d_in[3];
    const float* w1b = (const float*)d_in[4];
    const float* w2  = (const float*)d_in[5];
    const float* w2b = (const float*)d_in[6];
    float* out = (float*)d_out;

    static cudaStream_t s2 = nullptr;
    static cudaEvent_t evFork = nullptr, evW1 = nullptr, evW2 = nullptr;
    if (!s2) {
        cudaStreamCreateWithFlags(&s2, cudaStreamNonBlocking);
        cudaEventCreateWithFlags(&evFork, cudaEventDisableTiming);
        cudaEventCreateWithFlags(&evW1,  cudaEventDisableTiming);
        cudaEventCreateWithFlags(&evW2,  cudaEventDisableTiming);
    }

    cudaFuncSetAttribute(k_gemm1, cudaFuncAttributeMaxDynamicSharedMemorySize, NSTG * STAGE);
    cudaFuncSetAttribute(k_gemm2, cudaFuncAttributeMaxDynamicSharedMemorySize, NSTG * STAGE);

    __half* w1h; cudaGetSymbolAddress((void**)&w1h, g_w1h);
    __half* w2h; cudaGetSymbolAddress((void**)&w2h, g_w2h);

    // fork: w1 convert (evW1), then w2 convert (evW2), on s2
    cudaEventRecord(evFork, 0);
    cudaStreamWaitEvent(s2, evFork, 0);
    k_cvt_h<<<2048, 256, 0, s2>>>((const float4*)w1, (uint2*)w1h, (E_ * 2 * FFN_ * HID_) / 4);
    cudaEventRecord(evW1, s2);
    k_cvt_h<<<2048, 256, 0, s2>>>((const float4*)w2, (uint2*)w2h, (E_ * HID_ * FFN_) / 4);
    cudaEventRecord(evW2, s2);

    // main: router(+x cvt), scan(+counter reset), place(+pos map)
    k_router<<<M_TOK / 8, 256>>>(x, rw, rb, out);
    k_scan<<<1, 32>>>();
    k_place<<<NSLOT / 256, 256>>>();

    // join: GEMM1 needs w1h; GEMM2 needs w2h
    cudaStreamWaitEvent(0, evW1, 0);
    dim3 g1(FFN_ / 64, NSLOT / 128, E_);
    k_gemm1<<<g1, 256, NSTG * STAGE>>>(w1b);

    cudaStreamWaitEvent(0, evW2, 0);
    dim3 g2(HID_ / 128, NSLOT / 128, E_);
    k_gemm2<<<g2, 256, NSTG * STAGE>>>(w2b);

    // combine the two expert partials per token into out
    k_combine<<<OUT_MAIN / 4 / 256, 256>>>(out);
}

// round 16
// speedup vs baseline: 1.1448x; 1.0136x over previous
#include <cuda_runtime.h>
#include <cuda_fp16.h>
#include <cstdint>

#define E_       8
#define TOPK_    2
#define HID_     1024
#define FFN_     2048
#define M_TOK    2048
#define NSLOT    (M_TOK * TOPK_)      // 4096
#define OUT_MAIN (M_TOK * HID_)       // 2097152

#define BK    32
#define LDSW  40                      // smem row stride in halves (80B)
#define ROWB  80
#define ABUF  (128 * ROWB)            // 10240 B per operand tile
#define STAGE (2 * ABUF)              // 20480 B per stage (A + B)
#define NSTG  4

// ---------------- device scratch ----------------
__device__ int    g_cnt[E_];
__device__ int    g_off[E_ + 1];
__device__ int    g_cur[E_];
__device__ int    g_slot_e[NSLOT];
__device__ float  g_slot_w[NSLOT];
__device__ int    g_tok[NSLOT];
__device__ float  g_w[NSLOT];
__device__ int    g_pos[NSLOT];                         // slot -> grouped position
__device__ float  g_part[(size_t)NSLOT * HID_];         // 16 MB per-slot partials
__device__ __half g_hh[(size_t)NSLOT * FFN_];
__device__ __half g_xh[(size_t)M_TOK * HID_];
__device__ __half g_w1h[(size_t)E_ * 2 * FFN_ * HID_];
__device__ __half g_w2h[(size_t)E_ * HID_ * FFN_];

// ---------------- helpers ----------------
__device__ __forceinline__ void mma_f16(float* d, const uint32_t* a,
                                        const uint32_t* b, const float* c) {
    asm("mma.sync.aligned.m16n8k16.row.col.f32.f16.f16.f32 "
        "{%0,%1,%2,%3}, {%4,%5,%6,%7}, {%8,%9}, {%10,%11,%12,%13};\n"
        : "=f"(d[0]), "=f"(d[1]), "=f"(d[2]), "=f"(d[3])
        : "r"(a[0]), "r"(a[1]), "r"(a[2]), "r"(a[3]),
          "r"(b[0]), "r"(b[1]),
          "f"(c[0]), "f"(c[1]), "f"(c[2]), "f"(c[3]));
}
__device__ __forceinline__ void ldsm_x4(uint32_t& r0, uint32_t& r1,
                                        uint32_t& r2, uint32_t& r3, uint32_t addr) {
    asm volatile("ldmatrix.sync.aligned.m8n8.x4.shared.b16 {%0,%1,%2,%3}, [%4];"
                 : "=r"(r0), "=r"(r1), "=r"(r2), "=r"(r3) : "r"(addr));
}
__device__ __forceinline__ void cpa16(uint32_t saddr, const void* g) {
    asm volatile("cp.async.cg.shared.global [%0], [%1], 16;\n" :: "r"(saddr), "l"(g));
}
__device__ __forceinline__ void cpa_commit() { asm volatile("cp.async.commit_group;\n"); }
__device__ __forceinline__ void cpa_wait2()  { asm volatile("cp.async.wait_group 2;\n"); }
__device__ __forceinline__ void cpa_wait1()  { asm volatile("cp.async.wait_group 1;\n"); }
__device__ __forceinline__ void cpa_wait0()  { asm volatile("cp.async.wait_group 0;\n"); }
__device__ __forceinline__ uint32_t smem_u32(const void* p) {
    return (uint32_t)__cvta_generic_to_shared(p);
}

// ---------------- router (float4 loads) + fused x->fp16 ----------------
__global__ void k_router(const float* __restrict__ x,
                         const float* __restrict__ rw,
                         const float* __restrict__ rb,
                         float* __restrict__ out) {
    int warp = (blockIdx.x * blockDim.x + threadIdx.x) >> 5;
    int lane = threadIdx.x & 31;
    if (warp >= M_TOK) return;

    const float4* xr4 = (const float4*)(x + (size_t)warp * HID_);
    float4 xv[8];
#pragma unroll
    for (int j = 0; j < 8; j++) xv[j] = xr4[lane + 32 * j];

    uint2* xh2 = (uint2*)(g_xh + (size_t)warp * HID_);
#pragma unroll
    for (int j = 0; j < 8; j++) {
        __half2 lo = __floats2half2_rn(xv[j].x, xv[j].y);
        __half2 hi = __floats2half2_rn(xv[j].z, xv[j].w);
        uint2 o; o.x = *(uint32_t*)&lo; o.y = *(uint32_t*)&hi;
        xh2[lane + 32 * j] = o;
    }

    float logits[E_];
#pragma unroll
    for (int e = 0; e < E_; e++) {
        const float4* w4 = (const float4*)(rw + (size_t)e * HID_);
        float acc = 0.0f;
#pragma unroll
        for (int j = 0; j < 8; j++) {
            float4 w = w4[lane + 32 * j];
            acc += xv[j].x * w.x + xv[j].y * w.y + xv[j].z * w.z + xv[j].w * w.w;
        }
#pragma unroll
        for (int o = 16; o > 0; o >>= 1) acc += __shfl_xor_sync(0xffffffffu, acc, o);
        logits[e] = acc + rb[e];
    }

    if (lane == 0) {
        float mx = logits[0];
#pragma unroll
        for (int e = 1; e < E_; e++) mx = fmaxf(mx, logits[e]);
        float p[E_], s = 0.0f;
#pragma unroll
        for (int e = 0; e < E_; e++) { p[e] = expf(logits[e] - mx); s += p[e]; }
        float inv = 1.0f / s;
#pragma unroll
        for (int e = 0; e < E_; e++) p[e] *= inv;

        int i0 = 0;
#pragma unroll
        for (int e = 1; e < E_; e++) if (p[e] > p[i0]) i0 = e;
        int i1 = -1;
#pragma unroll
        for (int e = 0; e < E_; e++) {
            if (e == i0) continue;
            if (i1 < 0 || p[e] > p[i1]) i1 = e;
        }

        out[OUT_MAIN + warp * 2 + 0] = p[i0];
        out[OUT_MAIN + warp * 2 + 1] = p[i1];
        g_slot_e[warp * 2 + 0] = i0;  g_slot_w[warp * 2 + 0] = p[i0];
        g_slot_e[warp * 2 + 1] = i1;  g_slot_w[warp * 2 + 1] = p[i1];
        atomicAdd(&g_cnt[i0], 1);
        atomicAdd(&g_cnt[i1], 1);
    }
}

// scan: compute offsets, reset counters for next replay
__global__ void k_scan() {
    if (threadIdx.x == 0) {
        int s = 0;
        for (int e = 0; e < E_; e++) { g_off[e] = s; g_cur[e] = s; s += g_cnt[e]; g_cnt[e] = 0; }
        g_off[E_] = s;
    }
}

__global__ void k_place() {
    int s = blockIdx.x * blockDim.x + threadIdx.x;
    if (s >= NSLOT) return;
    int e = g_slot_e[s];
    int p = atomicAdd(&g_cur[e], 1);
    g_tok[p] = s >> 1;
    g_w[p]   = g_slot_w[s];
    g_pos[s] = p;
}

// fp32 -> fp16 streaming convert (RN)
__global__ void k_cvt_h(const float4* __restrict__ src, uint2* __restrict__ dst, int n4) {
    int i = blockIdx.x * blockDim.x + threadIdx.x;
    int stride = gridDim.x * blockDim.x;
    for (; i < n4; i += stride) {
        float4 v = src[i];
        __half2 lo = __floats2half2_rn(v.x, v.y);
        __half2 hi = __floats2half2_rn(v.z, v.w);
        uint2 o;
        o.x = *(uint32_t*)&lo;
        o.y = *(uint32_t*)&hi;
        dst[i] = o;
    }
}

// combine: out[t] = part[pos(2t)] + part[pos(2t+1)]
__global__ void k_combine(float* __restrict__ out) {
    int idx = blockIdx.x * blockDim.x + threadIdx.x;
    int t = idx >> 8;
    int j = idx & 255;
    const float4* p0 = (const float4*)(g_part + (size_t)g_pos[2 * t] * HID_);
    const float4* p1 = (const float4*)(g_part + (size_t)g_pos[2 * t + 1] * HID_);
    float4 a = p0[j], b = p1[j];
    float4 r;
    r.x = a.x + b.x; r.y = a.y + b.y; r.z = a.z + b.z; r.w = a.w + b.w;
    ((float4*)out)[idx] = r;
}

// ============================================================================
// GEMM1 (fp16 HMMA + ldmatrix, single-sync mainloop)
// ============================================================================
__global__ void __launch_bounds__(256, 2)
k_gemm1(const float* __restrict__ w1b) {
    int e = blockIdx.z;
    int rowEnd = g_off[e + 1];
    int row0 = g_off[e] + blockIdx.y * 128;
    if (row0 >= rowEnd) return;
    int nb = blockIdx.x * 64;

    extern __shared__ __half dsm[];
    __shared__ const __half* s_aptr[128];

    int tid  = threadIdx.x;
    int lane = tid & 31;
    int wid  = tid >> 5;
    int wm   = wid >> 2;
    int wn   = wid & 3;
    uint32_t sbase = smem_u32(dsm);

    for (int r = tid; r < 128; r += 256) {
        int gr = row0 + r;
        if (gr >= rowEnd) gr = rowEnd - 1;
        s_aptr[r] = g_xh + (size_t)g_tok[gr] * HID_;
    }
    __syncthreads();

    int rI[2], cI[2];
    const __half* bp[2];
#pragma unroll
    for (int i = 0; i < 2; i++) {
        int idx = tid + 256 * i;
        rI[i] = idx >> 2;
        cI[i] = (idx & 3) * 8;
        int r = rI[i];
        size_t wrow = (size_t)e * 2 * FFN_ + ((r & 1) ? (FFN_ + nb + (r >> 1)) : (nb + (r >> 1)));
        bp[i] = g_w1h + wrow * HID_;
    }

    auto load_tile = [&](int s, int k0) {
        uint32_t st = sbase + s * STAGE;
#pragma unroll
        for (int i = 0; i < 2; i++) {
            uint32_t off = (uint32_t)(rI[i] * LDSW + cI[i]) * 2;
            cpa16(st + off,        s_aptr[rI[i]] + k0 + cI[i]);
            cpa16(st + ABUF + off, bp[i] + k0 + cI[i]);
        }
        cpa_commit();
    };

    float acc[4][4][4];
#pragma unroll
    for (int mi = 0; mi < 4; mi++)
#pragma unroll
        for (int ni = 0; ni < 4; ni++)
#pragma unroll
            for (int q = 0; q < 4; q++) acc[mi][ni][q] = 0.0f;

    const int NT = HID_ / BK;   // 32
    load_tile(0, 0);
    load_tile(1, BK);
    load_tile(2, 2 * BK);

    int lr = lane >> 2;
    int lc = lane & 3;

    uint32_t a_loff = (uint32_t)((lane & 15) * ROWB + ((lane >> 4) & 1) * 16)
                    + (uint32_t)(wm * 64 * ROWB);
    uint32_t b_loff = (uint32_t)((((lane >> 4) & 1) * 8 + (lane & 7)) * ROWB
                    + ((lane >> 3) & 1) * 16)
                    + (uint32_t)(wn * 32 * ROWB);

    for (int kt = 0; kt < NT; kt++) {
        int buf = kt & (NSTG - 1);
        // ensure tile kt resident (outstanding groups: kt .. min(kt+2, NT-1))
        if (kt + 2 < NT)      { cpa_wait2(); }
        else if (kt + 1 < NT) { cpa_wait1(); }
        else                  { cpa_wait0(); }
        __syncthreads();                       // all threads done with tile kt-1
        if (kt + 3 < NT) load_tile((kt + 3) & (NSTG - 1), (kt + 3) * BK);

        uint32_t At = sbase + buf * STAGE;
        uint32_t Bt = At + ABUF;
#pragma unroll
        for (int s = 0; s < 2; s++) {
            uint32_t ks = s * 32;
            uint32_t a[4][4], b[4][2];
#pragma unroll
            for (int mi = 0; mi < 4; mi++)
                ldsm_x4(a[mi][0], a[mi][1], a[mi][2], a[mi][3],
                        At + (uint32_t)(mi * 16 * ROWB) + ks + a_loff);
#pragma unroll
            for (int nj = 0; nj < 2; nj++)
                ldsm_x4(b[2 * nj][0], b[2 * nj][1], b[2 * nj + 1][0], b[2 * nj + 1][1],
                        Bt + (uint32_t)(nj * 16 * ROWB) + ks + b_loff);
#pragma unroll
            for (int mi = 0; mi < 4; mi++)
#pragma unroll
                for (int ni = 0; ni < 4; ni++)
                    mma_f16(acc[mi][ni], a[mi], b[ni], acc[mi][ni]);
        }
    }

    const float* bg_base = w1b + (size_t)e * 2 * FFN_;
    const float* bu_base = bg_base + FFN_;
#pragma unroll
    for (int mi = 0; mi < 4; mi++) {
        int r = row0 + wm * 64 + mi * 16 + lr;
#pragma unroll
        for (int ni = 0; ni < 4; ni++) {
            int gj = nb + wn * 16 + ni * 4 + lc;
            float bg = bg_base[gj];
            float bu = bu_base[gj];
            if (r < rowEnd) {
                float g = acc[mi][ni][0] + bg;
                float u = acc[mi][ni][1] + bu;
                g_hh[(size_t)r * FFN_ + gj] = __float2half_rn((g / (1.0f + expf(-g))) * u);
            }
            if (r + 8 < rowEnd) {
                float g = acc[mi][ni][2] + bg;
                float u = acc[mi][ni][3] + bu;
                g_hh[(size_t)(r + 8) * FFN_ + gj] = __float2half_rn((g / (1.0f + expf(-g))) * u);
            }
        }
    }
}

// ============================================================================
// GEMM2 (fp16 HMMA + ldmatrix, single-sync mainloop): part = (h@W2^T + b2)*w
// ============================================================================
__global__ void __launch_bounds__(256, 2)
k_gemm2(const float* __restrict__ w2b) {
    int e = blockIdx.z;
    int rowEnd = g_off[e + 1];
    int row0 = g_off[e] + blockIdx.y * 128;
    if (row0 >= rowEnd) return;
    int nb = blockIdx.x * 128;

    extern __shared__ __half dsm[];

    int tid  = threadIdx.x;
    int lane = tid & 31;
    int wid  = tid >> 5;
    int wm   = wid >> 2;
    int wn   = wid & 3;
    uint32_t sbase = smem_u32(dsm);

    int rI[2], cI[2];
    const __half* ap[2];
    const __half* bp[2];
#pragma unroll
    for (int i = 0; i < 2; i++) {
        int idx = tid + 256 * i;
        rI[i] = idx >> 2;
        cI[i] = (idx & 3) * 8;
        int gr = row0 + rI[i];
        if (gr >= rowEnd) gr = rowEnd - 1;
        ap[i] = g_hh + (size_t)gr * FFN_;
        bp[i] = g_w2h + ((size_t)e * HID_ + (nb + rI[i])) * FFN_;
    }

    auto load_tile = [&](int s, int k0) {
        uint32_t st = sbase + s * STAGE;
#pragma unroll
        for (int i = 0; i < 2; i++) {
            uint32_t off = (uint32_t)(rI[i] * LDSW + cI[i]) * 2;
            cpa16(st + off,        ap[i] + k0 + cI[i]);
            cpa16(st + ABUF + off, bp[i] + k0 + cI[i]);
        }
        cpa_commit();
    };

    float acc[4][4][4];
#pragma unroll
    for (int mi = 0; mi < 4; mi++)
#pragma unroll
        for (int ni = 0; ni < 4; ni++)
#pragma unroll
            for (int q = 0; q < 4; q++) acc[mi][ni][q] = 0.0f;

    const int NT = FFN_ / BK;   // 64
    load_tile(0, 0);
    load_tile(1, BK);
    load_tile(2, 2 * BK);

    int lr = lane >> 2;
    int lc = lane & 3;

    uint32_t a_loff = (uint32_t)((lane & 15) * ROWB + ((lane >> 4) & 1) * 16)
                    + (uint32_t)(wm * 64 * ROWB);
    uint32_t b_loff = (uint32_t)((((lane >> 4) & 1) * 8 + (lane & 7)) * ROWB
                    + ((lane >> 3) & 1) * 16)
                    + (uint32_t)(wn * 32 * ROWB);

    for (int kt = 0; kt < NT; kt++) {
        int buf = kt & (NSTG - 1);
        if (kt + 2 < NT)      { cpa_wait2(); }
        else if (kt + 1 < NT) { cpa_wait1(); }
        else                  { cpa_wait0(); }
        __syncthreads();
        if (kt + 3 < NT) load_tile((kt + 3) & (NSTG - 1), (kt + 3) * BK);

        uint32_t At = sbase + buf * STAGE;
        uint32_t Bt = At + ABUF;
#pragma unroll
        for (int s = 0; s < 2; s++) {
            uint32_t ks = s * 32;
            uint32_t a[4][4], b[4][2];
#pragma unroll
            for (int mi = 0; mi < 4; mi++)
                ldsm_x4(a[mi][0], a[mi][1], a[mi][2], a[mi][3],
                        At + (uint32_t)(mi * 16 * ROWB) + ks + a_loff);
#pragma unroll
            for (int nj = 0; nj < 2; nj++)
                ldsm_x4(b[2 * nj][0], b[2 * nj][1], b[2 * nj + 1][0], b[2 * nj + 1][1],
                        Bt + (uint32_t)(nj * 16 * ROWB) + ks + b_loff);
#pragma unroll
            for (int mi = 0; mi < 4; mi++)
#pragma unroll
                for (int ni = 0; ni < 4; ni++)
                    mma_f16(acc[mi][ni], a[mi], b[ni], acc[mi][ni]);
        }
    }

    const float* b2 = w2b + (size_t)e * HID_;
#pragma unroll
    for (int mi = 0; mi < 4; mi++) {
        int r = row0 + wm * 64 + mi * 16 + lr;
#pragma unroll
        for (int ni = 0; ni < 4; ni++) {
            int c = nb + wn * 32 + ni * 8 + lc * 2;
            float b0 = b2[c], b1 = b2[c + 1];
            if (r < rowEnd) {
                float w = g_w[r];
                float2 v = make_float2((acc[mi][ni][0] + b0) * w,
                                       (acc[mi][ni][1] + b1) * w);
                *(float2*)(g_part + (size_t)r * HID_ + c) = v;
            }
            if (r + 8 < rowEnd) {
                float w = g_w[r + 8];
                float2 v = make_float2((acc[mi][ni][2] + b0) * w,
                                       (acc[mi][ni][3] + b1) * w);
                *(float2*)(g_part + (size_t)(r + 8) * HID_ + c) = v;
            }
        }
    }
}

// ---------------- launch ----------------
extern "C" void kernel_launch(void* const* d_in, const int* in_sizes, int n_in,
                              void* d_out, int out_size) {
    (void)in_sizes; (void)n_in; (void)out_size;
    const float* x   = (const float*)d_in[0];
    const float* rw  = (const float*)d_in[1];
    const float* rb  = (const float*)d_in[2];
    const float* w1  = (const float*)d_in[3];
    const float* w1b = (const float*)d_in[4];
    const float* w2  = (const float*)d_in[5];
    const float* w2b = (const float*)d_in[6];
    float* out = (float*)d_out;

    static cudaStream_t s2 = nullptr;
    static cudaEvent_t evFork = nullptr, evW1 = nullptr, evW2 = nullptr;
    if (!s2) {
        cudaStreamCreateWithFlags(&s2, cudaStreamNonBlocking);
        cudaEventCreateWithFlags(&evFork, cudaEventDisableTiming);
        cudaEventCreateWithFlags(&evW1,  cudaEventDisableTiming);
        cudaEventCreateWithFlags(&evW2,  cudaEventDisableTiming);
    }

    cudaFuncSetAttribute(k_gemm1, cudaFuncAttributeMaxDynamicSharedMemorySize, NSTG * STAGE);
    cudaFuncSetAttribute(k_gemm2, cudaFuncAttributeMaxDynamicSharedMemorySize, NSTG * STAGE);

    __half* w1h; cudaGetSymbolAddress((void**)&w1h, g_w1h);
    __half* w2h; cudaGetSymbolAddress((void**)&w2h, g_w2h);

    // fork: w1 convert (evW1), then w2 convert (evW2), on s2
    cudaEventRecord(evFork, 0);
    cudaStreamWaitEvent(s2, evFork, 0);
    k_cvt_h<<<2048, 256, 0, s2>>>((const float4*)w1, (uint2*)w1h, (E_ * 2 * FFN_ * HID_) / 4);
    cudaEventRecord(evW1, s2);
    k_cvt_h<<<2048, 256, 0, s2>>>((const float4*)w2, (uint2*)w2h, (E_ * HID_ * FFN_) / 4);
    cudaEventRecord(evW2, s2);

    // main: router(+x cvt), scan(+counter reset), place(+pos map)
    k_router<<<M_TOK / 8, 256>>>(x, rw, rb, out);
    k_scan<<<1, 32>>>();
    k_place<<<NSLOT / 256, 256>>>();

    // join: GEMM1 needs w1h; GEMM2 needs w2h
    cudaStreamWaitEvent(0, evW1, 0);
    dim3 g1(FFN_ / 64, NSLOT / 128, E_);
    k_gemm1<<<g1, 256, NSTG * STAGE>>>(w1b);

    cudaStreamWaitEvent(0, evW2, 0);
    dim3 g2(HID_ / 128, NSLOT / 128, E_);
    k_gemm2<<<g2, 256, NSTG * STAGE>>>(w2b);

    // combine the two expert partials per token into out
    k_combine<<<OUT_MAIN / 4 / 256, 256>>>(out);
}